// round 16
// baseline (speedup 1.0000x reference)
#include <cuda_runtime.h>
#include <math.h>

#define DIM     512
#define MNODES  90
#define KKEEP   45
#define TEN_LC  23
#define TEN_RC  22
#define MAXN    184320           // B*M = 2048*90
#define ROWF4   (DIM / 4)        // 128 float4 per row

__device__ unsigned char g_slot8[MAXN];   // slot-in-graph (0..44), 255 = dropped

__device__ __forceinline__ bool precedes(float ka, int va, float kb, int vb) {
    return (ka > kb) || (ka == kb && va < vb);   // score desc, id asc tiebreak
}

// ---------------------------------------------------------------------------
// Fused: score (2 rows/warp-iter, MLP=8) -> warp-register sort -> select ->
// gather (2 slots/warp-iter, MLP=8). One block (512 thr) per graph.
// ---------------------------------------------------------------------------
__global__ __launch_bounds__(512) void k_fused(
    const float4* __restrict__ x4, const float4* __restrict__ w4,
    float4* __restrict__ out_x,
    float* __restrict__ out_batch, float* __restrict__ out_perm,
    float* __restrict__ out_permlab)
{
    __shared__ float4 ws[ROWF4];
    __shared__ float  sk[128];
    __shared__ int    sv[128];
    __shared__ float  red[16];
    __shared__ int    warp_tot[4];
    __shared__ int    sel_gid[KKEEP];
    __shared__ float  sel_sc[KKEEP];
    __shared__ float  s_inv;

    const int t = threadIdx.x, b = blockIdx.x;
    const int warp = t >> 5, lane = t & 31;

    // ---- weight + 1/||w|| ----
    float4 wv = make_float4(0.f, 0.f, 0.f, 0.f);
    if (t < ROWF4) { wv = w4[t]; ws[t] = wv; }
    float ss = wv.x * wv.x + wv.y * wv.y + wv.z * wv.z + wv.w * wv.w;
#pragma unroll
    for (int o = 16; o; o >>= 1) ss += __shfl_xor_sync(0xffffffffu, ss, o);
    if (lane == 0) red[warp] = ss;
    if (t < MNODES) g_slot8[b * MNODES + t] = 255;   // default: dropped
    __syncthreads();
    if (t == 0) {
        float a = 0.f;
#pragma unroll
        for (int i = 0; i < 16; i++) a += red[i];
        s_inv = rsqrtf(a);
    }
    __syncthreads();

    // ---- scores: TWO rows per warp iteration (8 loads in flight) ----
    for (int r = warp; r < MNODES; r += 32) {
        const int r1 = r + 16;
        const bool has1 = (r1 < MNODES);
        const float4* x0 = x4 + (size_t)(b * MNODES + r) * ROWF4;
        const float4* x1 = x4 + (size_t)(b * MNODES + (has1 ? r1 : r)) * ROWF4;
        float s0 = 0.f, s1 = 0.f;
#pragma unroll
        for (int i = 0; i < 4; i++) {
            float4 a0 = x0[lane + 32 * i];
            float4 a1 = x1[lane + 32 * i];
            float4 wb = ws[lane + 32 * i];
            s0 += a0.x * wb.x + a0.y * wb.y + a0.z * wb.z + a0.w * wb.w;
            s1 += a1.x * wb.x + a1.y * wb.y + a1.z * wb.z + a1.w * wb.w;
        }
        float t0 = s0 + __shfl_xor_sync(0xffffffffu, s0, 16);
        float t1 = s1 + __shfl_xor_sync(0xffffffffu, s1, 16);
        float v = (lane < 16) ? t0 : t1;
#pragma unroll
        for (int o = 8; o; o >>= 1) v += __shfl_xor_sync(0xffffffffu, v, o);
        if (lane == 0) sk[r] = tanhf(v * s_inv);
        if (lane == 16 && has1) sk[r1] = tanhf(v * s_inv);
    }
    __syncthreads();

    // ---- warp-0 register bitonic sort of 128 (key desc, id asc) ----
    if (warp == 0) {
        float k[4]; int v[4];
#pragma unroll
        for (int j = 0; j < 4; j++) {
            int e = j * 32 + lane;
            k[j] = (e < MNODES) ? sk[e] : -INFINITY;
            v[j] = e;
        }
#pragma unroll
        for (int size = 2; size <= 128; size <<= 1) {
#pragma unroll
            for (int stride = size >> 1; stride > 0; stride >>= 1) {
                if (stride >= 32) {
                    const int s32 = stride >> 5;
#pragma unroll
                    for (int j = 0; j < 4; j++) {
                        int jp = j ^ s32;
                        if (jp > j) {
                            int e = j * 32 + lane;
                            bool dd  = ((e & size) == 0);
                            bool pre = precedes(k[j], v[j], k[jp], v[jp]);
                            if (dd ? !pre : pre) {
                                float tk = k[j]; k[j] = k[jp]; k[jp] = tk;
                                int   tv = v[j]; v[j] = v[jp]; v[jp] = tv;
                            }
                        }
                    }
                } else {
#pragma unroll
                    for (int j = 0; j < 4; j++) {
                        float kp = __shfl_xor_sync(0xffffffffu, k[j], stride);
                        int   vp = __shfl_xor_sync(0xffffffffu, v[j], stride);
                        int e = j * 32 + lane;
                        bool dd   = ((e & size) == 0);
                        bool low  = ((lane & stride) == 0);
                        bool pre  = precedes(k[j], v[j], kp, vp);
                        bool take = dd ? (low ? !pre : pre)
                                       : (low ? pre : !pre);
                        if (take) { k[j] = kp; v[j] = vp; }
                    }
                }
            }
        }
#pragma unroll
        for (int j = 0; j < 4; j++) {
            sk[j * 32 + lane] = k[j];
            sv[j * 32 + lane] = v[j];
        }
    }
    __syncthreads();

    if (t < MNODES)
        out_permlab[b * MNODES + t] = (float)(b * MNODES + sv[t]);

    // ---- category selection via ballot prefix scan ----
    int flag = 0, excl = 0;
    if (t < 128) flag = (t < MNODES && ((sv[t] & 1) == 0)) ? 1 : 0;
    if (warp < 4) {
        unsigned ball = __ballot_sync(0xffffffffu, flag);
        excl = __popc(ball & ((1u << lane) - 1u));
        if (lane == 0) warp_tot[warp] = __popc(ball);
    }
    __syncthreads();
    if (t < MNODES) {
        int base = 0;
        for (int i = 0; i < warp; i++) base += warp_tot[i];
        int ev = base + excl;
        int od = t - ev;
        int slot = -1;
        if (flag) { if (ev < TEN_LC) slot = ev; }
        else      { if (od < TEN_RC) slot = TEN_LC + od; }
        if (slot >= 0) {
            int gid = b * MNODES + sv[t];
            int jj  = b * KKEEP + slot;
            sel_gid[slot] = gid;
            sel_sc[slot]  = sk[t];
            g_slot8[gid]  = (unsigned char)slot;
            out_perm[jj]  = (float)gid;
            out_batch[jj] = (float)b;
        }
    }
    __syncthreads();

    // ---- gather: TWO slots per warp iteration (8 loads in flight) ----
    {
        const int s0 = warp, s1 = warp + 16;   // both < 32 <= KKEEP-?  (s1<45)
        {
            int g0 = sel_gid[s0], g1 = sel_gid[s1];
            float c0 = sel_sc[s0], c1 = sel_sc[s1];
            const float4* p0 = x4 + (size_t)g0 * ROWF4;
            const float4* p1 = x4 + (size_t)g1 * ROWF4;
            float4*       d0 = out_x + (size_t)(b * KKEEP + s0) * ROWF4;
            float4*       d1 = out_x + (size_t)(b * KKEEP + s1) * ROWF4;
            float4 a0[4], a1[4];
#pragma unroll
            for (int i = 0; i < 4; i++) {
                a0[i] = p0[lane + 32 * i];
                a1[i] = p1[lane + 32 * i];
            }
#pragma unroll
            for (int i = 0; i < 4; i++) {
                a0[i].x *= c0; a0[i].y *= c0; a0[i].z *= c0; a0[i].w *= c0;
                a1[i].x *= c1; a1[i].y *= c1; a1[i].z *= c1; a1[i].w *= c1;
                __stcs(d0 + lane + 32 * i, a0[i]);
                __stcs(d1 + lane + 32 * i, a1[i]);
            }
        }
        const int s2 = warp + 32;
        if (s2 < KKEEP) {
            int g2 = sel_gid[s2];
            float c2 = sel_sc[s2];
            const float4* p2 = x4 + (size_t)g2 * ROWF4;
            float4*       d2 = out_x + (size_t)(b * KKEEP + s2) * ROWF4;
#pragma unroll
            for (int i = 0; i < 4; i++) {
                float4 a = p2[lane + 32 * i];
                a.x *= c2; a.y *= c2; a.z *= c2; a.w *= c2;
                __stcs(d2 + lane + 32 * i, a);
            }
        }
    }
}

// ---------------------------------------------------------------------------
// Edge relabel + mask. Persistent CTAs, full slot table in SMEM, 1024 thr.
// ---------------------------------------------------------------------------
__device__ __forceinline__ float map_id(const unsigned char* s_tab, int gid,
                                        bool& ok) {
    unsigned slot = s_tab[gid];
    ok = (slot != 255u);
    unsigned b = (unsigned)gid / 90u;
    return ok ? (float)(b * KKEEP + slot) : -1.f;
}

__global__ __launch_bounds__(1024) void k_edges(
    const int4* __restrict__ ei0, const int4* __restrict__ ei1,
    long long E4,
    float4* __restrict__ oe0, float4* __restrict__ oe1,
    float4* __restrict__ om)
{
    extern __shared__ unsigned char s_tab[];   // MAXN bytes = 180 KB

    const uint4* src = (const uint4*)g_slot8;
    uint4* dst = (uint4*)s_tab;
    for (int i = threadIdx.x; i < MAXN / 16; i += blockDim.x)
        dst[i] = src[i];
    __syncthreads();

    long long stride = (long long)gridDim.x * blockDim.x;
    for (long long i = blockIdx.x * (long long)blockDim.x + threadIdx.x;
         i < E4; i += stride) {
        int4 r4 = __ldcs(ei0 + i);
        int4 c4 = __ldcs(ei1 + i);
        bool mr0, mr1, mr2, mr3, mc0, mc1, mc2, mc3;
        float fr0 = map_id(s_tab, r4.x, mr0);
        float fr1 = map_id(s_tab, r4.y, mr1);
        float fr2 = map_id(s_tab, r4.z, mr2);
        float fr3 = map_id(s_tab, r4.w, mr3);
        float fc0 = map_id(s_tab, c4.x, mc0);
        float fc1 = map_id(s_tab, c4.y, mc1);
        float fc2 = map_id(s_tab, c4.z, mc2);
        float fc3 = map_id(s_tab, c4.w, mc3);
        bool m0 = mr0 && mc0, m1 = mr1 && mc1;
        bool m2 = mr2 && mc2, m3 = mr3 && mc3;
        __stcs(oe0 + i, make_float4(m0 ? fr0 : -1.f, m1 ? fr1 : -1.f,
                                    m2 ? fr2 : -1.f, m3 ? fr3 : -1.f));
        __stcs(oe1 + i, make_float4(m0 ? fc0 : -1.f, m1 ? fc1 : -1.f,
                                    m2 ? fc2 : -1.f, m3 ? fc3 : -1.f));
        __stcs(om + i,  make_float4(m0 ? 1.f : 0.f, m1 ? 1.f : 0.f,
                                    m2 ? 1.f : 0.f, m3 ? 1.f : 0.f));
    }
}

// ---------------------------------------------------------------------------
extern "C" void kernel_launch(void* const* d_in, const int* in_sizes, int n_in,
                              void* d_out, int out_size) {
    const float* x  = (const float*)d_in[0];
    const float* w  = (const float*)d_in[1];
    const int*   ei = (const int*)d_in[2];

    int N = in_sizes[0] / DIM;         // 184320
    int B = N / MNODES;                // 2048
    long long E = (long long)in_sizes[2] / 2;

    float* out = (float*)d_out;
    size_t off_edge    = (size_t)B * KKEEP * DIM;
    size_t off_batch   = off_edge + 2 * (size_t)E;
    size_t off_perm    = off_batch + (size_t)B * KKEEP;
    size_t off_permlab = off_perm + (size_t)B * KKEEP;
    size_t off_mask    = off_permlab + (size_t)N;

    static bool attr_set = false;
    if (!attr_set) {
        cudaFuncSetAttribute(k_edges, cudaFuncAttributeMaxDynamicSharedMemorySize,
                             MAXN);
        attr_set = true;
    }

    k_fused<<<B, 512>>>((const float4*)x, (const float4*)w,
                        (float4*)out,
                        out + off_batch, out + off_perm, out + off_permlab);

    long long E4 = E / 4;
    k_edges<<<148, 1024, MAXN>>>((const int4*)ei, (const int4*)(ei + E), E4,
                                 (float4*)(out + off_edge),
                                 (float4*)(out + off_edge + E),
                                 (float4*)(out + off_mask));
}

// round 17
// speedup vs baseline: 1.1158x; 1.1158x over previous
#include <cuda_runtime.h>
#include <math.h>

#define DIM     512
#define MNODES  90
#define KKEEP   45
#define TEN_LC  23
#define TEN_RC  22
#define MAXN    184320           // B*M = 2048*90
#define ROWF4   (DIM / 4)        // 128 float4 per row

__device__ unsigned char g_slot8[MAXN];   // slot-in-graph (0..44), 255 = dropped

__device__ __forceinline__ bool precedes(float ka, int va, float kb, int vb) {
    return (ka > kb) || (ka == kb && va < vb);   // score desc, id asc tiebreak
}

// ---------------------------------------------------------------------------
// Fused: score (2 rows/warp-iter, MLP=8) -> warp-register sort -> select ->
// gather. One block (512 thr) per graph.
// (Banked optimum — measured 115.9 us total.)
// ---------------------------------------------------------------------------
__global__ __launch_bounds__(512) void k_fused(
    const float4* __restrict__ x4, const float4* __restrict__ w4,
    float4* __restrict__ out_x,
    float* __restrict__ out_batch, float* __restrict__ out_perm,
    float* __restrict__ out_permlab)
{
    __shared__ float4 ws[ROWF4];
    __shared__ float  sk[128];
    __shared__ int    sv[128];
    __shared__ float  red[16];
    __shared__ int    warp_tot[4];
    __shared__ int    sel_gid[KKEEP];
    __shared__ float  sel_sc[KKEEP];
    __shared__ float  s_inv;

    const int t = threadIdx.x, b = blockIdx.x;
    const int warp = t >> 5, lane = t & 31;

    // ---- weight + 1/||w|| ----
    float4 wv = make_float4(0.f, 0.f, 0.f, 0.f);
    if (t < ROWF4) { wv = w4[t]; ws[t] = wv; }
    float ss = wv.x * wv.x + wv.y * wv.y + wv.z * wv.z + wv.w * wv.w;
#pragma unroll
    for (int o = 16; o; o >>= 1) ss += __shfl_xor_sync(0xffffffffu, ss, o);
    if (lane == 0) red[warp] = ss;
    if (t < MNODES) g_slot8[b * MNODES + t] = 255;   // default: dropped
    __syncthreads();
    if (t == 0) {
        float a = 0.f;
#pragma unroll
        for (int i = 0; i < 16; i++) a += red[i];
        s_inv = rsqrtf(a);
    }
    __syncthreads();

    // ---- scores: TWO rows per warp iteration (8 loads in flight) ----
    for (int r = warp; r < MNODES; r += 32) {
        const int r1 = r + 16;
        const bool has1 = (r1 < MNODES);
        const float4* x0 = x4 + (size_t)(b * MNODES + r) * ROWF4;
        const float4* x1 = x4 + (size_t)(b * MNODES + (has1 ? r1 : r)) * ROWF4;
        float s0 = 0.f, s1 = 0.f;
#pragma unroll
        for (int i = 0; i < 4; i++) {
            float4 a0 = x0[lane + 32 * i];
            float4 a1 = x1[lane + 32 * i];
            float4 wb = ws[lane + 32 * i];
            s0 += a0.x * wb.x + a0.y * wb.y + a0.z * wb.z + a0.w * wb.w;
            s1 += a1.x * wb.x + a1.y * wb.y + a1.z * wb.z + a1.w * wb.w;
        }
#pragma unroll
        for (int o = 16; o; o >>= 1) {
            s0 += __shfl_xor_sync(0xffffffffu, s0, o);
            s1 += __shfl_xor_sync(0xffffffffu, s1, o);
        }
        if (lane == 0) {
            sk[r] = tanhf(s0 * s_inv);
            if (has1) sk[r1] = tanhf(s1 * s_inv);
        }
    }
    __syncthreads();

    // ---- warp-0 register bitonic sort of 128 (key desc, id asc) ----
    if (warp == 0) {
        float k[4]; int v[4];
#pragma unroll
        for (int j = 0; j < 4; j++) {
            int e = j * 32 + lane;
            k[j] = (e < MNODES) ? sk[e] : -INFINITY;
            v[j] = e;
        }
#pragma unroll
        for (int size = 2; size <= 128; size <<= 1) {
#pragma unroll
            for (int stride = size >> 1; stride > 0; stride >>= 1) {
                if (stride >= 32) {
                    const int s32 = stride >> 5;
#pragma unroll
                    for (int j = 0; j < 4; j++) {
                        int jp = j ^ s32;
                        if (jp > j) {
                            int e = j * 32 + lane;
                            bool dd  = ((e & size) == 0);
                            bool pre = precedes(k[j], v[j], k[jp], v[jp]);
                            if (dd ? !pre : pre) {
                                float tk = k[j]; k[j] = k[jp]; k[jp] = tk;
                                int   tv = v[j]; v[j] = v[jp]; v[jp] = tv;
                            }
                        }
                    }
                } else {
#pragma unroll
                    for (int j = 0; j < 4; j++) {
                        float kp = __shfl_xor_sync(0xffffffffu, k[j], stride);
                        int   vp = __shfl_xor_sync(0xffffffffu, v[j], stride);
                        int e = j * 32 + lane;
                        bool dd   = ((e & size) == 0);
                        bool low  = ((lane & stride) == 0);
                        bool pre  = precedes(k[j], v[j], kp, vp);
                        bool take = dd ? (low ? !pre : pre)
                                       : (low ? pre : !pre);
                        if (take) { k[j] = kp; v[j] = vp; }
                    }
                }
            }
        }
#pragma unroll
        for (int j = 0; j < 4; j++) {
            sk[j * 32 + lane] = k[j];
            sv[j * 32 + lane] = v[j];
        }
    }
    __syncthreads();

    if (t < MNODES)
        out_permlab[b * MNODES + t] = (float)(b * MNODES + sv[t]);

    // ---- category selection via ballot prefix scan ----
    int flag = 0, excl = 0;
    if (t < 128) flag = (t < MNODES && ((sv[t] & 1) == 0)) ? 1 : 0;
    if (warp < 4) {
        unsigned ball = __ballot_sync(0xffffffffu, flag);
        excl = __popc(ball & ((1u << lane) - 1u));
        if (lane == 0) warp_tot[warp] = __popc(ball);
    }
    __syncthreads();
    if (t < MNODES) {
        int base = 0;
        for (int i = 0; i < warp; i++) base += warp_tot[i];
        int ev = base + excl;
        int od = t - ev;
        int slot = -1;
        if (flag) { if (ev < TEN_LC) slot = ev; }
        else      { if (od < TEN_RC) slot = TEN_LC + od; }
        if (slot >= 0) {
            int gid = b * MNODES + sv[t];
            int jj  = b * KKEEP + slot;
            sel_gid[slot] = gid;
            sel_sc[slot]  = sk[t];
            g_slot8[gid]  = (unsigned char)slot;
            out_perm[jj]  = (float)gid;
            out_batch[jj] = (float)b;
        }
    }
    __syncthreads();

    // ---- gather selected rows (mostly L2-hot), scale, streaming store ----
    for (int slot = warp; slot < KKEEP; slot += 16) {
        int gid  = sel_gid[slot];
        float sc = sel_sc[slot];
        const float4* src = x4 + (size_t)gid * ROWF4;
        float4*       dst = out_x + (size_t)(b * KKEEP + slot) * ROWF4;
#pragma unroll
        for (int i = 0; i < 4; i++) {
            float4 a = src[lane + 32 * i];
            a.x *= sc; a.y *= sc; a.z *= sc; a.w *= sc;
            __stcs(dst + lane + 32 * i, a);
        }
    }
}

// ---------------------------------------------------------------------------
// Edge relabel + mask. Persistent CTAs, full slot table in SMEM, 1024 thr.
// ---------------------------------------------------------------------------
__device__ __forceinline__ float map_id(const unsigned char* s_tab, int gid,
                                        bool& ok) {
    unsigned slot = s_tab[gid];
    ok = (slot != 255u);
    unsigned b = (unsigned)gid / 90u;
    return ok ? (float)(b * KKEEP + slot) : -1.f;
}

__global__ __launch_bounds__(1024) void k_edges(
    const int4* __restrict__ ei0, const int4* __restrict__ ei1,
    long long E4,
    float4* __restrict__ oe0, float4* __restrict__ oe1,
    float4* __restrict__ om)
{
    extern __shared__ unsigned char s_tab[];   // MAXN bytes = 180 KB

    const uint4* src = (const uint4*)g_slot8;
    uint4* dst = (uint4*)s_tab;
    for (int i = threadIdx.x; i < MAXN / 16; i += blockDim.x)
        dst[i] = src[i];
    __syncthreads();

    long long stride = (long long)gridDim.x * blockDim.x;
    for (long long i = blockIdx.x * (long long)blockDim.x + threadIdx.x;
         i < E4; i += stride) {
        int4 r4 = __ldcs(ei0 + i);
        int4 c4 = __ldcs(ei1 + i);
        bool mr0, mr1, mr2, mr3, mc0, mc1, mc2, mc3;
        float fr0 = map_id(s_tab, r4.x, mr0);
        float fr1 = map_id(s_tab, r4.y, mr1);
        float fr2 = map_id(s_tab, r4.z, mr2);
        float fr3 = map_id(s_tab, r4.w, mr3);
        float fc0 = map_id(s_tab, c4.x, mc0);
        float fc1 = map_id(s_tab, c4.y, mc1);
        float fc2 = map_id(s_tab, c4.z, mc2);
        float fc3 = map_id(s_tab, c4.w, mc3);
        bool m0 = mr0 && mc0, m1 = mr1 && mc1;
        bool m2 = mr2 && mc2, m3 = mr3 && mc3;
        __stcs(oe0 + i, make_float4(m0 ? fr0 : -1.f, m1 ? fr1 : -1.f,
                                    m2 ? fr2 : -1.f, m3 ? fr3 : -1.f));
        __stcs(oe1 + i, make_float4(m0 ? fc0 : -1.f, m1 ? fc1 : -1.f,
                                    m2 ? fc2 : -1.f, m3 ? fc3 : -1.f));
        __stcs(om + i,  make_float4(m0 ? 1.f : 0.f, m1 ? 1.f : 0.f,
                                    m2 ? 1.f : 0.f, m3 ? 1.f : 0.f));
    }
}

// ---------------------------------------------------------------------------
extern "C" void kernel_launch(void* const* d_in, const int* in_sizes, int n_in,
                              void* d_out, int out_size) {
    const float* x  = (const float*)d_in[0];
    const float* w  = (const float*)d_in[1];
    const int*   ei = (const int*)d_in[2];

    int N = in_sizes[0] / DIM;         // 184320
    int B = N / MNODES;                // 2048
    long long E = (long long)in_sizes[2] / 2;

    float* out = (float*)d_out;
    size_t off_edge    = (size_t)B * KKEEP * DIM;
    size_t off_batch   = off_edge + 2 * (size_t)E;
    size_t off_perm    = off_batch + (size_t)B * KKEEP;
    size_t off_permlab = off_perm + (size_t)B * KKEEP;
    size_t off_mask    = off_permlab + (size_t)N;

    static bool attr_set = false;
    if (!attr_set) {
        cudaFuncSetAttribute(k_edges, cudaFuncAttributeMaxDynamicSharedMemorySize,
                             MAXN);
        attr_set = true;
    }

    k_fused<<<B, 512>>>((const float4*)x, (const float4*)w,
                        (float4*)out,
                        out + off_batch, out + off_perm, out + off_permlab);

    long long E4 = E / 4;
    k_edges<<<148, 1024, MAXN>>>((const int4*)ei, (const int4*)(ei + E), E4,
                                 (float4*)(out + off_edge),
                                 (float4*)(out + off_edge + E),
                                 (float4*)(out + off_mask));
}